// round 16
// baseline (speedup 1.0000x reference)
#include <cuda_runtime.h>
#include <cstdint>

#define NB 2
#define NH 16
#define NS 2048
#define ND 64
#define NSPLIT 4            /* split-K factor: 8 k-tiles per block */

// Scratch (allocation-free rule: __device__ globals)
// g_Q/g_K/g_V hold tf32-rounded bit patterns (Q pre-scaled by 1/8),
// produced by proj kernel, consumed raw by attn (bit-identical to R5 math).
__device__ float g_Q[NB*NH*NS*ND];
__device__ float g_K[NB*NH*NS*ND];
__device__ float g_V[NB*NH*NS*ND];
// split-K partials: unnormalized A, row max m, row denom l, per quarter
__device__ float g_pA[NSPLIT][NB*NH][NS][ND];   // 67 MB
__device__ float g_pm[NSPLIT][NB*NH][NS];
__device__ float g_pl[NSPLIT][NB*NH][NS];

// ---------------------------------------------------------------------------
// helpers
// ---------------------------------------------------------------------------
__device__ __forceinline__ uint32_t f2tf32(float x) {
    uint32_t r;
    asm("cvt.rna.tf32.f32 %0, %1;" : "=r"(r) : "f"(x));
    return r;
}
// m16n8k8 tf32 warp MMA, fp32 accumulate (base ISA, works on sm_103 target)
__device__ __forceinline__ void mma8(float* c, const uint32_t* a,
                                     uint32_t b0, uint32_t b1) {
    asm volatile(
        "mma.sync.aligned.m16n8k8.row.col.f32.tf32.tf32.f32 "
        "{%0,%1,%2,%3}, {%4,%5,%6,%7}, {%8,%9}, {%0,%1,%2,%3};"
        : "+f"(c[0]), "+f"(c[1]), "+f"(c[2]), "+f"(c[3])
        : "r"(a[0]), "r"(a[1]), "r"(a[2]), "r"(a[3]), "r"(b0), "r"(b1));
}
__device__ __forceinline__ uint32_t smem_u32(const void* p) {
    uint32_t a;
    asm("{ .reg .u64 t; cvta.to.shared.u64 t, %1; cvt.u32.u64 %0, t; }"
        : "=r"(a) : "l"(p));
    return a;
}
__device__ __forceinline__ void cpasync16(uint32_t dst, const void* src) {
    asm volatile("cp.async.cg.shared.global [%0], [%1], 16;"
                 :: "r"(dst), "l"(src));
}
#define CP_COMMIT() asm volatile("cp.async.commit_group;" ::: "memory")
#define CP_WAIT0()  asm volatile("cp.async.wait_group 0;" ::: "memory")

// ---------------------------------------------------------------------------
// JAX partitionable threefry2x32, key=(0,42): bits[i] = o0^o1, counter (0,i)
// R5/R10 form (best measured). Executed between cp.async issue and wait so
// the ALU work hides the K/V GMEM->SMEM latency.
// ---------------------------------------------------------------------------
__device__ __forceinline__ uint32_t rotl32(uint32_t x, int r) {
    return __funnelshift_l(x, x, r);
}
#define KEEP_THRESH 0xE6666600u   // uniform < 0.9f, exact integer reduction

// returns bit0 = keep(e), bit1 = keep(e+1); two interleaved ciphers for ILP
__device__ __forceinline__ uint32_t keep2(uint32_t e) {
    const uint32_t k0 = 0u, k1 = 42u, k2 = 0u ^ 42u ^ 0x1BD11BDAu;
    uint32_t a0 = k0, b0 = e + k1;
    uint32_t a1 = k0, b1 = e + 1u + k1;
#define TF_R2(r) { a0 += b0; b0 = rotl32(b0, (r)) ^ a0;                        \
                   a1 += b1; b1 = rotl32(b1, (r)) ^ a1; }
    TF_R2(13) TF_R2(15) TF_R2(26) TF_R2(6)
    a0 += k1; a1 += k1; b0 += k2 + 1u; b1 += k2 + 1u;
    TF_R2(17) TF_R2(29) TF_R2(16) TF_R2(24)
    a0 += k2; a1 += k2; b0 += k0 + 2u; b1 += k0 + 2u;
    TF_R2(13) TF_R2(15) TF_R2(26) TF_R2(6)
    a0 += k0; a1 += k0; b0 += k1 + 3u; b1 += k1 + 3u;
    TF_R2(17) TF_R2(29) TF_R2(16) TF_R2(24)
    a0 += k1; a1 += k1; b0 += k2 + 4u; b1 += k2 + 4u;
    TF_R2(13) TF_R2(15) TF_R2(26) TF_R2(6)
    a0 += k2; a1 += k2; b0 += k0 + 5u; b1 += k0 + 5u;
#undef TF_R2
    uint32_t r = ((a0 ^ b0) < KEEP_THRESH) ? 1u : 0u;
    r |= ((a1 ^ b1) < KEEP_THRESH) ? 2u : 0u;
    return r;
}

// ---------------------------------------------------------------------------
// Tensor-core QKV projection with error-free Ozaki split:
//   X = Xh + Xl (exact), W = Wh + Wl (exact, tf32 splits)
//   Y = tf32_rna((Xh*Wh + Xl*Wh + Xh*Wl + bias) * scale)   [X_lo*W_lo ~2^-22]
// fp32-class accuracy; moves proj off the saturated FFMA pipe (49us at the
// fp32 ceiling) onto the idle tensor pipe.
// Block: 64 rows x {Q,K,V}, 128 threads = 4 warps. Output [B,H,S,D] layout.
// SMEM (uint32): Xh[64][68], Xl[64][68], Wh[64][68], Wl[64][68], bs[64].
// ---------------------------------------------------------------------------
#define PJ_XH 0
#define PJ_XL 4352
#define PJ_WH 8704
#define PJ_WL 13056
#define PJ_BS 17408
#define PJ_WORDS 17472      /* 69888 B */

__global__ __launch_bounds__(128) void proj_mma_kernel(
        const float* __restrict__ Xq, const float* __restrict__ Xk,
        const float* __restrict__ Xv,
        const float* __restrict__ Wq_, const float* __restrict__ Wk_,
        const float* __restrict__ Wv_,
        const float* __restrict__ bq_, const float* __restrict__ bk_,
        const float* __restrict__ bv_) {
    extern __shared__ __align__(16) uint32_t sm[];
    uint32_t* Xh = sm + PJ_XH;
    uint32_t* Xl = sm + PJ_XL;
    uint32_t* Wh = sm + PJ_WH;
    uint32_t* Wl = sm + PJ_WL;
    float*    bs = reinterpret_cast<float*>(sm + PJ_BS);

    int which = blockIdx.y;
    const float* X = (which == 0) ? Xq : (which == 1) ? Xk : Xv;
    const float* W = (which == 0) ? Wq_ : (which == 1) ? Wk_ : Wv_;
    const float* bias = (which == 0) ? bq_ : (which == 1) ? bk_ : bv_;
    float* Y = (which == 0) ? g_Q : (which == 1) ? g_K : g_V;
    float scale = (which == 0) ? 0.125f : 1.0f;

    int tid = threadIdx.x;
    int lane = tid & 31, w = tid >> 5;
    int gi = lane >> 2, ci = lane & 3;
    int r0 = blockIdx.x * 64;
    int row = tid >> 1, hf = tid & 1;

    if (tid < 64) bs[tid] = bias[tid];

    // ---- stage X and W with hi/lo tf32 split ----
    {
        const float4* Xg = reinterpret_cast<const float4*>(
            X + (size_t)(r0 + row) * 64) + hf * 8;
        const float4* Wg = reinterpret_cast<const float4*>(
            W + (size_t)row * 64) + hf * 8;
        uint32_t* xh = Xh + row * 68 + hf * 32;
        uint32_t* xl = Xl + row * 68 + hf * 32;
        uint32_t* wh = Wh + row * 68 + hf * 32;
        uint32_t* wl = Wl + row * 68 + hf * 32;
#pragma unroll
        for (int j = 0; j < 8; j++) {
            float4 v = Xg[j];
            uint4 h4, l4;
            h4.x = f2tf32(v.x); l4.x = f2tf32(v.x - __uint_as_float(h4.x));
            h4.y = f2tf32(v.y); l4.y = f2tf32(v.y - __uint_as_float(h4.y));
            h4.z = f2tf32(v.z); l4.z = f2tf32(v.z - __uint_as_float(h4.z));
            h4.w = f2tf32(v.w); l4.w = f2tf32(v.w - __uint_as_float(h4.w));
            *reinterpret_cast<uint4*>(xh + j * 4) = h4;
            *reinterpret_cast<uint4*>(xl + j * 4) = l4;
            v = Wg[j];
            h4.x = f2tf32(v.x); l4.x = f2tf32(v.x - __uint_as_float(h4.x));
            h4.y = f2tf32(v.y); l4.y = f2tf32(v.y - __uint_as_float(h4.y));
            h4.z = f2tf32(v.z); l4.z = f2tf32(v.z - __uint_as_float(h4.z));
            h4.w = f2tf32(v.w); l4.w = f2tf32(v.w - __uint_as_float(h4.w));
            *reinterpret_cast<uint4*>(wh + j * 4) = h4;
            *reinterpret_cast<uint4*>(wl + j * 4) = l4;
        }
    }
    __syncthreads();

    // ---- A fragments (rows w*16+gi, +8) for Xh and Xl ----
    uint32_t ah[8][4], al[8][4];
    {
        const uint32_t* XhR = Xh + (w * 16) * 68;
        const uint32_t* XlR = Xl + (w * 16) * 68;
#pragma unroll
        for (int kc = 0; kc < 8; kc++) {
            ah[kc][0] = XhR[gi * 68 + kc * 8 + ci];
            ah[kc][1] = XhR[(gi + 8) * 68 + kc * 8 + ci];
            ah[kc][2] = XhR[gi * 68 + kc * 8 + ci + 4];
            ah[kc][3] = XhR[(gi + 8) * 68 + kc * 8 + ci + 4];
            al[kc][0] = XlR[gi * 68 + kc * 8 + ci];
            al[kc][1] = XlR[(gi + 8) * 68 + kc * 8 + ci];
            al[kc][2] = XlR[gi * 68 + kc * 8 + ci + 4];
            al[kc][3] = XlR[(gi + 8) * 68 + kc * 8 + ci + 4];
        }
    }

    // ---- 3-term GEMM: s = Xh*Wh + Xl*Wh + Xh*Wl ----
    float s[8][4] = {};
#pragma unroll
    for (int kc = 0; kc < 8; kc++) {
#pragma unroll
        for (int nt = 0; nt < 8; nt++) {
            int off = (nt * 8 + gi) * 68 + kc * 8 + ci;
            uint32_t bh0 = Wh[off], bh1 = Wh[off + 4];
            uint32_t bl0 = Wl[off], bl1 = Wl[off + 4];
            mma8(s[nt], ah[kc], bh0, bh1);
            mma8(s[nt], al[kc], bh0, bh1);
            mma8(s[nt], ah[kc], bl0, bl1);
        }
    }

    // ---- epilogue: +bias, *scale, tf32 round, store [B,H,S,D] ----
    // rows in this block: h = gi (lo) / gi+8 (hi), same (b, sq) for both.
    int r = r0 + w * 16 + gi;
    int b = r >> 15;
    int sq = (r & 32767) >> 4;
    float* Ylo = Y + ((size_t)(b * NH + gi) * NS + sq) * ND;
    float* Yhi = Ylo + (size_t)8 * NS * ND;
#pragma unroll
    for (int nt = 0; nt < 8; nt++) {
        float2 bv = *reinterpret_cast<const float2*>(&bs[nt * 8 + 2 * ci]);
        uint2 u;
        u.x = f2tf32((s[nt][0] + bv.x) * scale);
        u.y = f2tf32((s[nt][1] + bv.y) * scale);
        *reinterpret_cast<uint2*>(Ylo + nt * 8 + 2 * ci) = u;
        u.x = f2tf32((s[nt][2] + bv.x) * scale);
        u.y = f2tf32((s[nt][3] + bv.y) * scale);
        *reinterpret_cast<uint2*>(Yhi + nt * 8 + 2 * ci) = u;
    }
}

// ---------------------------------------------------------------------------
// Warp-MMA (m16n8k8 tf32) flash attention with FUSED threefry dropout.
// R15 body (best: 689us), SPLIT-K = 4. Unchanged.
// ---------------------------------------------------------------------------
#define KS_OFF 0
#define VS_OFF 4352          /* 64*68 */
#define PS_OFF 8960          /* + 64*72 */
#define SMEM_WORDS 13312     /* + 4*16*68 */

__global__ __launch_bounds__(128, 3) void attn_mma_kernel(
        const float* __restrict__ mask) {
    extern __shared__ __align__(16) uint32_t sm[];
    uint32_t* Ks = sm + KS_OFF;
    uint32_t* Vs = sm + VS_OFF;
    uint32_t* Ps = sm + PS_OFF;
    uint32_t sb = smem_u32(sm);

    int tid = threadIdx.x;
    int lane = tid & 31, w = tid >> 5;       // 4 warps
    int gi = lane >> 2, ci = lane & 3;
    int qt = blockIdx.x >> 2, quarter = blockIdx.x & 3;
    int h = blockIdx.y, b = blockIdx.z;
    int bh = b * NH + h;
    int q0 = qt * 64;
    int kt0 = quarter * (32 / NSPLIT), kt1 = kt0 + (32 / NSPLIT);

    int row = tid >> 1, hf = tid & 1;        // staging: 64 rows x 2 halves

    // staging smem byte-addresses for this thread
    uint32_t ks_dst = sb + (KS_OFF + row * 68 + hf * 32) * 4;
    uint32_t vs_dst = sb + (VS_OFF + row * 72 + hf * 32) * 4;

    // ---- stage Q tile (already tf32+scaled) into Ps via cp.async ----
    {
        uint32_t ps_dst = sb + (PS_OFF + row * 68 + hf * 32) * 4;
        const float* Qg = g_Q + ((size_t)bh * NS + q0 + row) * ND + hf * 32;
#pragma unroll
        for (int j = 0; j < 8; j++)
            cpasync16(ps_dst + j * 16, Qg + j * 4);
        CP_COMMIT();
        CP_WAIT0();
    }
    __syncthreads();
    uint32_t qf[8][4];
    {
        const uint32_t* Qs = Ps + (w * 16) * 68;
#pragma unroll
        for (int kc = 0; kc < 8; kc++) {
            qf[kc][0] = Qs[gi * 68 + kc * 8 + ci];
            qf[kc][1] = Qs[(gi + 8) * 68 + kc * 8 + ci];
            qf[kc][2] = Qs[gi * 68 + kc * 8 + ci + 4];
            qf[kc][3] = Qs[(gi + 8) * 68 + kc * 8 + ci + 4];
        }
    }
    __syncthreads();   // Ps will be overwritten as P-buffer in the mainloop

    float oacc[8][4] = {};
    float m_lo = -3.0e38f, m_hi = -3.0e38f, l_lo = 0.f, l_hi = 0.f;

    int rlo = q0 + w * 16 + gi;              // rhi = rlo + 8 (derived)
    const float* mask_lo = mask + ((size_t)b * NS + rlo) * NS;
    // flat dropout-element base (hi base = lo + 8*NS, constant)
    uint32_t ebl = (uint32_t)(bh * NS + rlo) * NS + 2 * ci;

    const float* Kbase = g_K + ((size_t)bh * NS + row) * ND + hf * 32;
    const float* Vbase = g_V + ((size_t)bh * NS + row) * ND + hf * 32;

    for (int kt = kt0; kt < kt1; kt++) {
        // ---- issue K,V tile copies (GMEM -> SMEM, no registers) ----
        {
            const float* Kg = Kbase + (size_t)kt * 64 * ND;
            const float* Vg = Vbase + (size_t)kt * 64 * ND;
#pragma unroll
            for (int j = 0; j < 8; j++) {
                cpasync16(ks_dst + j * 16, Kg + j * 4);
                cpasync16(vs_dst + j * 16, Vg + j * 4);
            }
            CP_COMMIT();
        }

        // ---- fused threefry dropout, in the cp.async latency shadow ----
        uint32_t klo = 0u, khi = 0u;
        {
            uint32_t e0 = ebl + (uint32_t)kt * 64;
#pragma unroll 2
            for (int nt = 0; nt < 8; nt++) {
                klo |= keep2(e0 + nt * 8) << (2 * nt);
                khi |= keep2(e0 + 8u * NS + nt * 8) << (2 * nt);
            }
        }

        CP_WAIT0();
        __syncthreads();

        // ---- S = Q @ K^T ----
        float s[8][4] = {};
#pragma unroll
        for (int kc = 0; kc < 8; kc++) {
#pragma unroll
            for (int nt = 0; nt < 8; nt++) {
                uint32_t b0 = Ks[(nt * 8 + gi) * 68 + kc * 8 + ci];
                uint32_t b1 = Ks[(nt * 8 + gi) * 68 + kc * 8 + ci + 4];
                mma8(s[nt], qf[kc], b0, b1);
            }
        }

        // ---- mask + online softmax ----
        float mxl = -3.0e38f, mxh = -3.0e38f;
#pragma unroll
        for (int nt = 0; nt < 8; nt++) {
            const float* mrow = mask_lo + kt * 64 + nt * 8 + 2 * ci;
            float2 ml = *reinterpret_cast<const float2*>(mrow);
            float2 mh = *reinterpret_cast<const float2*>(mrow + 8 * NS);
            s[nt][0] += ml.x; s[nt][1] += ml.y;
            s[nt][2] += mh.x; s[nt][3] += mh.y;
            mxl = fmaxf(mxl, fmaxf(s[nt][0], s[nt][1]));
            mxh = fmaxf(mxh, fmaxf(s[nt][2], s[nt][3]));
        }
        mxl = fmaxf(mxl, __shfl_xor_sync(0xffffffffu, mxl, 1));
        mxl = fmaxf(mxl, __shfl_xor_sync(0xffffffffu, mxl, 2));
        mxh = fmaxf(mxh, __shfl_xor_sync(0xffffffffu, mxh, 1));
        mxh = fmaxf(mxh, __shfl_xor_sync(0xffffffffu, mxh, 2));

        float nml = fmaxf(m_lo, mxl), nmh = fmaxf(m_hi, mxh);
        float scl = __expf(m_lo - nml), sch = __expf(m_hi - nmh);
        m_lo = nml; m_hi = nmh;

        float suml = 0.f, sumh = 0.f;
#pragma unroll
        for (int nt = 0; nt < 8; nt++) {
            s[nt][0] = __expf(s[nt][0] - nml);
            s[nt][1] = __expf(s[nt][1] - nml);
            s[nt][2] = __expf(s[nt][2] - nmh);
            s[nt][3] = __expf(s[nt][3] - nmh);
            suml += s[nt][0] + s[nt][1];
            sumh += s[nt][2] + s[nt][3];
        }
        suml += __shfl_xor_sync(0xffffffffu, suml, 1);
        suml += __shfl_xor_sync(0xffffffffu, suml, 2);
        sumh += __shfl_xor_sync(0xffffffffu, sumh, 1);
        sumh += __shfl_xor_sync(0xffffffffu, sumh, 2);
        l_lo = l_lo * scl + suml;
        l_hi = l_hi * sch + sumh;
#pragma unroll
        for (int nt = 0; nt < 8; nt++) {
            oacc[nt][0] *= scl; oacc[nt][1] *= scl;
            oacc[nt][2] *= sch; oacc[nt][3] *= sch;
        }

        // ---- dropout apply + P store (per-warp private region) ----
        uint32_t* Pw = Ps + w * 16 * 68;
#pragma unroll
        for (int nt = 0; nt < 8; nt++) {
            int c0 = nt * 8 + 2 * ci;
            uint2 plo, phi;
            plo.x = ((klo >> (2 * nt)) & 1u)     ? f2tf32(s[nt][0]) : 0u;
            plo.y = ((klo >> (2 * nt + 1)) & 1u) ? f2tf32(s[nt][1]) : 0u;
            phi.x = ((khi >> (2 * nt)) & 1u)     ? f2tf32(s[nt][2]) : 0u;
            phi.y = ((khi >> (2 * nt + 1)) & 1u) ? f2tf32(s[nt][3]) : 0u;
            *reinterpret_cast<uint2*>(Pw + gi * 68 + c0) = plo;
            *reinterpret_cast<uint2*>(Pw + (gi + 8) * 68 + c0) = phi;
        }
        __syncwarp();

        // ---- O += P @ V ----
#pragma unroll
        for (int kc = 0; kc < 8; kc++) {
            uint32_t a[4];
            a[0] = Pw[gi * 68 + kc * 8 + ci];
            a[1] = Pw[(gi + 8) * 68 + kc * 8 + ci];
            a[2] = Pw[gi * 68 + kc * 8 + ci + 4];
            a[3] = Pw[(gi + 8) * 68 + kc * 8 + ci + 4];
#pragma unroll
            for (int nt = 0; nt < 8; nt++) {
                uint32_t b0 = Vs[(kc * 8 + ci) * 72 + nt * 8 + gi];
                uint32_t b1 = Vs[(kc * 8 + ci + 4) * 72 + nt * 8 + gi];
                mma8(oacc[nt], a, b0, b1);
            }
        }
        __syncthreads();
    }

    // epilogue: write unnormalized partial A + (m, l) per row
    float* pA = &g_pA[quarter][bh][rlo][0];
#pragma unroll
    for (int nt = 0; nt < 8; nt++) {
        float2 a, c;
        a.x = oacc[nt][0]; a.y = oacc[nt][1];
        c.x = oacc[nt][2]; c.y = oacc[nt][3];
        *reinterpret_cast<float2*>(pA + nt * 8 + 2 * ci) = a;
        *reinterpret_cast<float2*>(pA + 8 * ND + nt * 8 + 2 * ci) = c;
    }
    if (ci == 0) {
        g_pm[quarter][bh][rlo] = m_lo;     g_pl[quarter][bh][rlo] = l_lo;
        g_pm[quarter][bh][rlo + 8] = m_hi; g_pl[quarter][bh][rlo + 8] = l_hi;
    }
}

// ---------------------------------------------------------------------------
// Merge the four split-K quarters (unchanged from R15).
// ---------------------------------------------------------------------------
__global__ void merge_kernel(float* __restrict__ out) {
    int idx = blockIdx.x * blockDim.x + threadIdx.x;   // [0, 524288)
    int rowg = idx >> 3;                 // global row [0, 65536)
    int c0 = (idx & 7) << 3;             // column start
    int bh = rowg >> 11, s = rowg & 2047;

    float m = -3.0e38f;
#pragma unroll
    for (int i = 0; i < NSPLIT; i++) m = fmaxf(m, g_pm[i][bh][s]);
    float wgt[NSPLIT], lsum = 0.f;
#pragma unroll
    for (int i = 0; i < NSPLIT; i++) {
        wgt[i] = __expf(g_pm[i][bh][s] - m);
        lsum += wgt[i] * g_pl[i][bh][s];
    }
    float inv = 1.0f / (lsum * 0.9f);

    float4* O = reinterpret_cast<float4*>(out + ((size_t)bh * NS + s) * ND + c0);
#pragma unroll
    for (int j = 0; j < 2; j++) {
        float4 o = make_float4(0.f, 0.f, 0.f, 0.f);
#pragma unroll
        for (int i = 0; i < NSPLIT; i++) {
            float4 a = reinterpret_cast<const float4*>(&g_pA[i][bh][s][c0])[j];
            float sc = wgt[i] * inv;
            o.x += a.x * sc; o.y += a.y * sc;
            o.z += a.z * sc; o.w += a.w * sc;
        }
        O[j] = o;
    }
}

// ---------------------------------------------------------------------------
extern "C" void kernel_launch(void* const* d_in, const int* in_sizes, int n_in,
                              void* d_out, int out_size) {
    (void)in_sizes; (void)n_in; (void)out_size;
    const float* q   = (const float*)d_in[0];
    const float* k   = (const float*)d_in[1];
    const float* v   = (const float*)d_in[2];
    const float* msk = (const float*)d_in[3];
    const float* Wq  = (const float*)d_in[4];
    const float* bq  = (const float*)d_in[5];
    const float* Wk  = (const float*)d_in[6];
    const float* bk  = (const float*)d_in[7];
    const float* Wv  = (const float*)d_in[8];
    const float* bv  = (const float*)d_in[9];
    float* out = (float*)d_out;

    const int attn_smem = SMEM_WORDS * 4;    // 53248 B
    const int proj_smem = PJ_WORDS * 4;      // 69888 B
    cudaFuncSetAttribute(attn_mma_kernel,
                         cudaFuncAttributeMaxDynamicSharedMemorySize, attn_smem);
    cudaFuncSetAttribute(proj_mma_kernel,
                         cudaFuncAttributeMaxDynamicSharedMemorySize, proj_smem);

    dim3 pgrid(1024, 3);
    proj_mma_kernel<<<pgrid, 128, proj_smem>>>(q, k, v, Wq, Wk, Wv, bq, bk, bv);

    dim3 grid(NS / 64 * NSPLIT, NH, NB);     // qt*4 + quarter
    attn_mma_kernel<<<grid, 128, attn_smem>>>(msk);

    merge_kernel<<<2048, 256>>>(out);
}

// round 17
// speedup vs baseline: 1.0138x; 1.0138x over previous
#include <cuda_runtime.h>
#include <cstdint>

#define NB 2
#define NH 16
#define NS 2048
#define ND 64
#define NSPLIT 4            /* split-K factor: 8 k-tiles per block */

// Scratch (allocation-free rule: __device__ globals)
// g_Q/g_K/g_V hold tf32-rounded bit patterns (Q pre-scaled by 1/8),
// produced by proj kernel, consumed raw by attn (bit-identical to R5 math).
__device__ float g_Q[NB*NH*NS*ND];
__device__ float g_K[NB*NH*NS*ND];
__device__ float g_V[NB*NH*NS*ND];
// split-K partials: unnormalized A, row max m, row denom l, per quarter
__device__ float g_pA[NSPLIT][NB*NH][NS][ND];   // 67 MB
__device__ float g_pm[NSPLIT][NB*NH][NS];
__device__ float g_pl[NSPLIT][NB*NH][NS];

// ---------------------------------------------------------------------------
// helpers
// ---------------------------------------------------------------------------
__device__ __forceinline__ uint32_t f2tf32(float x) {
    uint32_t r;
    asm("cvt.rna.tf32.f32 %0, %1;" : "=r"(r) : "f"(x));
    return r;
}
// m16n8k8 tf32 warp MMA, fp32 accumulate (base ISA, works on sm_103 target)
__device__ __forceinline__ void mma8(float* c, const uint32_t* a,
                                     uint32_t b0, uint32_t b1) {
    asm volatile(
        "mma.sync.aligned.m16n8k8.row.col.f32.tf32.tf32.f32 "
        "{%0,%1,%2,%3}, {%4,%5,%6,%7}, {%8,%9}, {%0,%1,%2,%3};"
        : "+f"(c[0]), "+f"(c[1]), "+f"(c[2]), "+f"(c[3])
        : "r"(a[0]), "r"(a[1]), "r"(a[2]), "r"(a[3]), "r"(b0), "r"(b1));
}
__device__ __forceinline__ uint32_t smem_u32(const void* p) {
    uint32_t a;
    asm("{ .reg .u64 t; cvta.to.shared.u64 t, %1; cvt.u32.u64 %0, t; }"
        : "=r"(a) : "l"(p));
    return a;
}
__device__ __forceinline__ void cpasync16(uint32_t dst, const void* src) {
    asm volatile("cp.async.cg.shared.global [%0], [%1], 16;"
                 :: "r"(dst), "l"(src));
}
#define CP_COMMIT() asm volatile("cp.async.commit_group;" ::: "memory")
#define CP_WAIT0()  asm volatile("cp.async.wait_group 0;" ::: "memory")

// ---------------------------------------------------------------------------
// JAX partitionable threefry2x32, key=(0,42): bits[i] = o0^o1, counter (0,i)
// R5/R10 form (best measured). Executed between cp.async issue and wait so
// the ALU work hides the K/V GMEM->SMEM latency.
// ---------------------------------------------------------------------------
__device__ __forceinline__ uint32_t rotl32(uint32_t x, int r) {
    return __funnelshift_l(x, x, r);
}
#define KEEP_THRESH 0xE6666600u   // uniform < 0.9f, exact integer reduction

// returns bit0 = keep(e), bit1 = keep(e+1); two interleaved ciphers for ILP
__device__ __forceinline__ uint32_t keep2(uint32_t e) {
    const uint32_t k0 = 0u, k1 = 42u, k2 = 0u ^ 42u ^ 0x1BD11BDAu;
    uint32_t a0 = k0, b0 = e + k1;
    uint32_t a1 = k0, b1 = e + 1u + k1;
#define TF_R2(r) { a0 += b0; b0 = rotl32(b0, (r)) ^ a0;                        \
                   a1 += b1; b1 = rotl32(b1, (r)) ^ a1; }
    TF_R2(13) TF_R2(15) TF_R2(26) TF_R2(6)
    a0 += k1; a1 += k1; b0 += k2 + 1u; b1 += k2 + 1u;
    TF_R2(17) TF_R2(29) TF_R2(16) TF_R2(24)
    a0 += k2; a1 += k2; b0 += k0 + 2u; b1 += k0 + 2u;
    TF_R2(13) TF_R2(15) TF_R2(26) TF_R2(6)
    a0 += k0; a1 += k0; b0 += k1 + 3u; b1 += k1 + 3u;
    TF_R2(17) TF_R2(29) TF_R2(16) TF_R2(24)
    a0 += k1; a1 += k1; b0 += k2 + 4u; b1 += k2 + 4u;
    TF_R2(13) TF_R2(15) TF_R2(26) TF_R2(6)
    a0 += k2; a1 += k2; b0 += k0 + 5u; b1 += k0 + 5u;
#undef TF_R2
    uint32_t r = ((a0 ^ b0) < KEEP_THRESH) ? 1u : 0u;
    r |= ((a1 ^ b1) < KEEP_THRESH) ? 2u : 0u;
    return r;
}

// ---------------------------------------------------------------------------
// Tensor-core QKV projection, Ozaki 3-term split (fp32-class accuracy):
//   Y = tf32_rna((Xh*Wh + Xl*Wh + Xh*Wl + bias) * scale)
// R16 was L1-bound (80.4%) at 23% issue. Fixes:
//   - Wh/Wl stored in (d,d+4)-PAIRED smem rows (stride 72, R6-validated):
//     each mma B-operand = ONE LDS.64  -> B-frag LDS halved (256->128)
//   - X staged RAW via cp.async; hi/lo split done at A-frag load in regs
//     -> staging traffic halved, smem 69.9KB -> 54.5KB -> 4 blocks/SM
// Block: 64 rows x {Q,K,V}, 128 threads = 4 warps. Output [B,H,S,D] layout.
// ---------------------------------------------------------------------------
#define PJ_X  0              /* raw X [64][68] */
#define PJ_WH 4352           /* paired Wh [64][72] */
#define PJ_WL 8960           /* paired Wl [64][72] */
#define PJ_BS 13568
#define PJ_WORDS 13632       /* 54528 B */

__global__ __launch_bounds__(128) void proj_mma_kernel(
        const float* __restrict__ Xq, const float* __restrict__ Xk,
        const float* __restrict__ Xv,
        const float* __restrict__ Wq_, const float* __restrict__ Wk_,
        const float* __restrict__ Wv_,
        const float* __restrict__ bq_, const float* __restrict__ bk_,
        const float* __restrict__ bv_) {
    extern __shared__ __align__(16) uint32_t sm[];
    float*    Xr  = reinterpret_cast<float*>(sm + PJ_X);
    uint32_t* Whp = sm + PJ_WH;
    uint32_t* Wlp = sm + PJ_WL;
    float*    bs  = reinterpret_cast<float*>(sm + PJ_BS);
    uint32_t sb = smem_u32(sm);

    int which = blockIdx.y;
    const float* X = (which == 0) ? Xq : (which == 1) ? Xk : Xv;
    const float* W = (which == 0) ? Wq_ : (which == 1) ? Wk_ : Wv_;
    const float* bias = (which == 0) ? bq_ : (which == 1) ? bk_ : bv_;
    float* Y = (which == 0) ? g_Q : (which == 1) ? g_K : g_V;
    float scale = (which == 0) ? 0.125f : 1.0f;

    int tid = threadIdx.x;
    int lane = tid & 31, w = tid >> 5;
    int gi = lane >> 2, ci = lane & 3;
    int r0 = blockIdx.x * 64;
    int row = tid >> 1, hf = tid & 1;

    // ---- stage X raw via cp.async (split deferred to A-frag load) ----
    {
        uint32_t x_dst = sb + (PJ_X + row * 68 + hf * 32) * 4;
        const float* Xg = X + (size_t)(r0 + row) * 64 + hf * 32;
#pragma unroll
        for (int j = 0; j < 8; j++)
            cpasync16(x_dst + j * 16, Xg + j * 4);
        CP_COMMIT();
    }
    // ---- stage W: hi/lo split into PAIRED layout (one LDS.64 per B-frag)
    {
        const float4* Wg = reinterpret_cast<const float4*>(
            W + (size_t)row * 64) + hf * 8;
        float4 t[8];
#pragma unroll
        for (int j = 0; j < 8; j++) t[j] = Wg[j];
#pragma unroll
        for (int kc = 0; kc < 4; kc++) {
            float4 f0 = t[2 * kc], f1 = t[2 * kc + 1];
            uint4 uh0, uh1, ul0, ul1;
            uh0.x = f2tf32(f0.x); ul0.x = f2tf32(f0.x - __uint_as_float(uh0.x));
            uh0.y = f2tf32(f1.x); ul0.y = f2tf32(f1.x - __uint_as_float(uh0.y));
            uh0.z = f2tf32(f0.y); ul0.z = f2tf32(f0.y - __uint_as_float(uh0.z));
            uh0.w = f2tf32(f1.y); ul0.w = f2tf32(f1.y - __uint_as_float(uh0.w));
            uh1.x = f2tf32(f0.z); ul1.x = f2tf32(f0.z - __uint_as_float(uh1.x));
            uh1.y = f2tf32(f1.z); ul1.y = f2tf32(f1.z - __uint_as_float(uh1.y));
            uh1.z = f2tf32(f0.w); ul1.z = f2tf32(f0.w - __uint_as_float(uh1.z));
            uh1.w = f2tf32(f1.w); ul1.w = f2tf32(f1.w - __uint_as_float(uh1.w));
            uint32_t* bh = Whp + row * 72 + (4 * hf + kc) * 8;
            uint32_t* bl = Wlp + row * 72 + (4 * hf + kc) * 8;
            *reinterpret_cast<uint4*>(bh) = uh0;
            *reinterpret_cast<uint4*>(bh + 4) = uh1;
            *reinterpret_cast<uint4*>(bl) = ul0;
            *reinterpret_cast<uint4*>(bl + 4) = ul1;
        }
    }
    if (tid < 64) bs[tid] = bias[tid];
    CP_WAIT0();
    __syncthreads();

    // ---- A fragments: load raw X, split hi/lo in registers ----
    uint32_t ah[8][4], al[8][4];
    {
        const float* XrR = Xr + (w * 16) * 68;
#pragma unroll
        for (int kc = 0; kc < 8; kc++) {
            int i0 = gi * 68 + kc * 8 + ci;
            float x;
            x = XrR[i0];
            ah[kc][0] = f2tf32(x);
            al[kc][0] = f2tf32(x - __uint_as_float(ah[kc][0]));
            x = XrR[i0 + 8 * 68];
            ah[kc][1] = f2tf32(x);
            al[kc][1] = f2tf32(x - __uint_as_float(ah[kc][1]));
            x = XrR[i0 + 4];
            ah[kc][2] = f2tf32(x);
            al[kc][2] = f2tf32(x - __uint_as_float(ah[kc][2]));
            x = XrR[i0 + 8 * 68 + 4];
            ah[kc][3] = f2tf32(x);
            al[kc][3] = f2tf32(x - __uint_as_float(ah[kc][3]));
        }
    }

    // ---- 3-term GEMM: s = Xh*Wh + Xl*Wh + Xh*Wl (LDS.64 B-frags) ----
    float s[8][4] = {};
#pragma unroll
    for (int kc = 0; kc < 8; kc++) {
#pragma unroll
        for (int nt = 0; nt < 8; nt++) {
            int off = (nt * 8 + gi) * 72 + kc * 8 + ci * 2;
            uint2 bh = *reinterpret_cast<const uint2*>(Whp + off);
            uint2 bl = *reinterpret_cast<const uint2*>(Wlp + off);
            mma8(s[nt], ah[kc], bh.x, bh.y);
            mma8(s[nt], al[kc], bh.x, bh.y);
            mma8(s[nt], ah[kc], bl.x, bl.y);
        }
    }

    // ---- epilogue: +bias, *scale, tf32 round, store [B,H,S,D] ----
    int r = r0 + w * 16 + gi;
    int b = r >> 15;
    int sq = (r & 32767) >> 4;
    float* Ylo = Y + ((size_t)(b * NH + gi) * NS + sq) * ND;
    float* Yhi = Ylo + (size_t)8 * NS * ND;
#pragma unroll
    for (int nt = 0; nt < 8; nt++) {
        float2 bv = *reinterpret_cast<const float2*>(&bs[nt * 8 + 2 * ci]);
        uint2 u;
        u.x = f2tf32((s[nt][0] + bv.x) * scale);
        u.y = f2tf32((s[nt][1] + bv.y) * scale);
        *reinterpret_cast<uint2*>(Ylo + nt * 8 + 2 * ci) = u;
        u.x = f2tf32((s[nt][2] + bv.x) * scale);
        u.y = f2tf32((s[nt][3] + bv.y) * scale);
        *reinterpret_cast<uint2*>(Yhi + nt * 8 + 2 * ci) = u;
    }
}

// ---------------------------------------------------------------------------
// Warp-MMA (m16n8k8 tf32) flash attention with FUSED threefry dropout.
// R15 body (best: 689us), SPLIT-K = 4. Unchanged.
// ---------------------------------------------------------------------------
#define KS_OFF 0
#define VS_OFF 4352          /* 64*68 */
#define PS_OFF 8960          /* + 64*72 */
#define SMEM_WORDS 13312     /* + 4*16*68 */

__global__ __launch_bounds__(128, 3) void attn_mma_kernel(
        const float* __restrict__ mask) {
    extern __shared__ __align__(16) uint32_t sm[];
    uint32_t* Ks = sm + KS_OFF;
    uint32_t* Vs = sm + VS_OFF;
    uint32_t* Ps = sm + PS_OFF;
    uint32_t sb = smem_u32(sm);

    int tid = threadIdx.x;
    int lane = tid & 31, w = tid >> 5;       // 4 warps
    int gi = lane >> 2, ci = lane & 3;
    int qt = blockIdx.x >> 2, quarter = blockIdx.x & 3;
    int h = blockIdx.y, b = blockIdx.z;
    int bh = b * NH + h;
    int q0 = qt * 64;
    int kt0 = quarter * (32 / NSPLIT), kt1 = kt0 + (32 / NSPLIT);

    int row = tid >> 1, hf = tid & 1;        // staging: 64 rows x 2 halves

    // staging smem byte-addresses for this thread
    uint32_t ks_dst = sb + (KS_OFF + row * 68 + hf * 32) * 4;
    uint32_t vs_dst = sb + (VS_OFF + row * 72 + hf * 32) * 4;

    // ---- stage Q tile (already tf32+scaled) into Ps via cp.async ----
    {
        uint32_t ps_dst = sb + (PS_OFF + row * 68 + hf * 32) * 4;
        const float* Qg = g_Q + ((size_t)bh * NS + q0 + row) * ND + hf * 32;
#pragma unroll
        for (int j = 0; j < 8; j++)
            cpasync16(ps_dst + j * 16, Qg + j * 4);
        CP_COMMIT();
        CP_WAIT0();
    }
    __syncthreads();
    uint32_t qf[8][4];
    {
        const uint32_t* Qs = Ps + (w * 16) * 68;
#pragma unroll
        for (int kc = 0; kc < 8; kc++) {
            qf[kc][0] = Qs[gi * 68 + kc * 8 + ci];
            qf[kc][1] = Qs[(gi + 8) * 68 + kc * 8 + ci];
            qf[kc][2] = Qs[gi * 68 + kc * 8 + ci + 4];
            qf[kc][3] = Qs[(gi + 8) * 68 + kc * 8 + ci + 4];
        }
    }
    __syncthreads();   // Ps will be overwritten as P-buffer in the mainloop

    float oacc[8][4] = {};
    float m_lo = -3.0e38f, m_hi = -3.0e38f, l_lo = 0.f, l_hi = 0.f;

    int rlo = q0 + w * 16 + gi;              // rhi = rlo + 8 (derived)
    const float* mask_lo = mask + ((size_t)b * NS + rlo) * NS;
    // flat dropout-element base (hi base = lo + 8*NS, constant)
    uint32_t ebl = (uint32_t)(bh * NS + rlo) * NS + 2 * ci;

    const float* Kbase = g_K + ((size_t)bh * NS + row) * ND + hf * 32;
    const float* Vbase = g_V + ((size_t)bh * NS + row) * ND + hf * 32;

    for (int kt = kt0; kt < kt1; kt++) {
        // ---- issue K,V tile copies (GMEM -> SMEM, no registers) ----
        {
            const float* Kg = Kbase + (size_t)kt * 64 * ND;
            const float* Vg = Vbase + (size_t)kt * 64 * ND;
#pragma unroll
            for (int j = 0; j < 8; j++) {
                cpasync16(ks_dst + j * 16, Kg + j * 4);
                cpasync16(vs_dst + j * 16, Vg + j * 4);
            }
            CP_COMMIT();
        }

        // ---- fused threefry dropout, in the cp.async latency shadow ----
        uint32_t klo = 0u, khi = 0u;
        {
            uint32_t e0 = ebl + (uint32_t)kt * 64;
#pragma unroll 2
            for (int nt = 0; nt < 8; nt++) {
                klo |= keep2(e0 + nt * 8) << (2 * nt);
                khi |= keep2(e0 + 8u * NS + nt * 8) << (2 * nt);
            }
        }

        CP_WAIT0();
        __syncthreads();

        // ---- S = Q @ K^T ----
        float s[8][4] = {};
#pragma unroll
        for (int kc = 0; kc < 8; kc++) {
#pragma unroll
            for (int nt = 0; nt < 8; nt++) {
                uint32_t b0 = Ks[(nt * 8 + gi) * 68 + kc * 8 + ci];
                uint32_t b1 = Ks[(nt * 8 + gi) * 68 + kc * 8 + ci + 4];
                mma8(s[nt], qf[kc], b0, b1);
            }
        }

        // ---- mask + online softmax ----
        float mxl = -3.0e38f, mxh = -3.0e38f;
#pragma unroll
        for (int nt = 0; nt < 8; nt++) {
            const float* mrow = mask_lo + kt * 64 + nt * 8 + 2 * ci;
            float2 ml = *reinterpret_cast<const float2*>(mrow);
            float2 mh = *reinterpret_cast<const float2*>(mrow + 8 * NS);
            s[nt][0] += ml.x; s[nt][1] += ml.y;
            s[nt][2] += mh.x; s[nt][3] += mh.y;
            mxl = fmaxf(mxl, fmaxf(s[nt][0], s[nt][1]));
            mxh = fmaxf(mxh, fmaxf(s[nt][2], s[nt][3]));
        }
        mxl = fmaxf(mxl, __shfl_xor_sync(0xffffffffu, mxl, 1));
        mxl = fmaxf(mxl, __shfl_xor_sync(0xffffffffu, mxl, 2));
        mxh = fmaxf(mxh, __shfl_xor_sync(0xffffffffu, mxh, 1));
        mxh = fmaxf(mxh, __shfl_xor_sync(0xffffffffu, mxh, 2));

        float nml = fmaxf(m_lo, mxl), nmh = fmaxf(m_hi, mxh);
        float scl = __expf(m_lo - nml), sch = __expf(m_hi - nmh);
        m_lo = nml; m_hi = nmh;

        float suml = 0.f, sumh = 0.f;
#pragma unroll
        for (int nt = 0; nt < 8; nt++) {
            s[nt][0] = __expf(s[nt][0] - nml);
            s[nt][1] = __expf(s[nt][1] - nml);
            s[nt][2] = __expf(s[nt][2] - nmh);
            s[nt][3] = __expf(s[nt][3] - nmh);
            suml += s[nt][0] + s[nt][1];
            sumh += s[nt][2] + s[nt][3];
        }
        suml += __shfl_xor_sync(0xffffffffu, suml, 1);
        suml += __shfl_xor_sync(0xffffffffu, suml, 2);
        sumh += __shfl_xor_sync(0xffffffffu, sumh, 1);
        sumh += __shfl_xor_sync(0xffffffffu, sumh, 2);
        l_lo = l_lo * scl + suml;
        l_hi = l_hi * sch + sumh;
#pragma unroll
        for (int nt = 0; nt < 8; nt++) {
            oacc[nt][0] *= scl; oacc[nt][1] *= scl;
            oacc[nt][2] *= sch; oacc[nt][3] *= sch;
        }

        // ---- dropout apply + P store (per-warp private region) ----
        uint32_t* Pw = Ps + w * 16 * 68;
#pragma unroll
        for (int nt = 0; nt < 8; nt++) {
            int c0 = nt * 8 + 2 * ci;
            uint2 plo, phi;
            plo.x = ((klo >> (2 * nt)) & 1u)     ? f2tf32(s[nt][0]) : 0u;
            plo.y = ((klo >> (2 * nt + 1)) & 1u) ? f2tf32(s[nt][1]) : 0u;
            phi.x = ((khi >> (2 * nt)) & 1u)     ? f2tf32(s[nt][2]) : 0u;
            phi.y = ((khi >> (2 * nt + 1)) & 1u) ? f2tf32(s[nt][3]) : 0u;
            *reinterpret_cast<uint2*>(Pw + gi * 68 + c0) = plo;
            *reinterpret_cast<uint2*>(Pw + (gi + 8) * 68 + c0) = phi;
        }
        __syncwarp();

        // ---- O += P @ V ----
#pragma unroll
        for (int kc = 0; kc < 8; kc++) {
            uint32_t a[4];
            a[0] = Pw[gi * 68 + kc * 8 + ci];
            a[1] = Pw[(gi + 8) * 68 + kc * 8 + ci];
            a[2] = Pw[gi * 68 + kc * 8 + ci + 4];
            a[3] = Pw[(gi + 8) * 68 + kc * 8 + ci + 4];
#pragma unroll
            for (int nt = 0; nt < 8; nt++) {
                uint32_t b0 = Vs[(kc * 8 + ci) * 72 + nt * 8 + gi];
                uint32_t b1 = Vs[(kc * 8 + ci + 4) * 72 + nt * 8 + gi];
                mma8(oacc[nt], a, b0, b1);
            }
        }
        __syncthreads();
    }

    // epilogue: write unnormalized partial A + (m, l) per row
    float* pA = &g_pA[quarter][bh][rlo][0];
#pragma unroll
    for (int nt = 0; nt < 8; nt++) {
        float2 a, c;
        a.x = oacc[nt][0]; a.y = oacc[nt][1];
        c.x = oacc[nt][2]; c.y = oacc[nt][3];
        *reinterpret_cast<float2*>(pA + nt * 8 + 2 * ci) = a;
        *reinterpret_cast<float2*>(pA + 8 * ND + nt * 8 + 2 * ci) = c;
    }
    if (ci == 0) {
        g_pm[quarter][bh][rlo] = m_lo;     g_pl[quarter][bh][rlo] = l_lo;
        g_pm[quarter][bh][rlo + 8] = m_hi; g_pl[quarter][bh][rlo + 8] = l_hi;
    }
}

// ---------------------------------------------------------------------------
// Merge the four split-K quarters (unchanged from R15).
// ---------------------------------------------------------------------------
__global__ void merge_kernel(float* __restrict__ out) {
    int idx = blockIdx.x * blockDim.x + threadIdx.x;   // [0, 524288)
    int rowg = idx >> 3;                 // global row [0, 65536)
    int c0 = (idx & 7) << 3;             // column start
    int bh = rowg >> 11, s = rowg & 2047;

    float m = -3.0e38f;
#pragma unroll
    for (int i = 0; i < NSPLIT; i++) m = fmaxf(m, g_pm[i][bh][s]);
    float wgt[NSPLIT], lsum = 0.f;
#pragma unroll
    for (int i = 0; i < NSPLIT; i++) {
        wgt[i] = __expf(g_pm[i][bh][s] - m);
        lsum += wgt[i] * g_pl[i][bh][s];
    }
    float inv = 1.0f / (lsum * 0.9f);

    float4* O = reinterpret_cast<float4*>(out + ((size_t)bh * NS + s) * ND + c0);
#pragma unroll
    for (int j = 0; j < 2; j++) {
        float4 o = make_float4(0.f, 0.f, 0.f, 0.f);
#pragma unroll
        for (int i = 0; i < NSPLIT; i++) {
            float4 a = reinterpret_cast<const float4*>(&g_pA[i][bh][s][c0])[j];
            float sc = wgt[i] * inv;
            o.x += a.x * sc; o.y += a.y * sc;
            o.z += a.z * sc; o.w += a.w * sc;
        }
        O[j] = o;
    }
}

// ---------------------------------------------------------------------------
extern "C" void kernel_launch(void* const* d_in, const int* in_sizes, int n_in,
                              void* d_out, int out_size) {
    (void)in_sizes; (void)n_in; (void)out_size;
    const float* q   = (const float*)d_in[0];
    const float* k   = (const float*)d_in[1];
    const float* v   = (const float*)d_in[2];
    const float* msk = (const float*)d_in[3];
    const float* Wq  = (const float*)d_in[4];
    const float* bq  = (const float*)d_in[5];
    const float* Wk  = (const float*)d_in[6];
    const float* bk  = (const float*)d_in[7];
    const float* Wv  = (const float*)d_in[8];
    const float* bv  = (const float*)d_in[9];
    float* out = (float*)d_out;

    const int attn_smem = SMEM_WORDS * 4;    // 53248 B
    const int proj_smem = PJ_WORDS * 4;      // 54528 B
    cudaFuncSetAttribute(attn_mma_kernel,
                         cudaFuncAttributeMaxDynamicSharedMemorySize, attn_smem);
    cudaFuncSetAttribute(proj_mma_kernel,
                         cudaFuncAttributeMaxDynamicSharedMemorySize, proj_smem);

    dim3 pgrid(1024, 3);
    proj_mma_kernel<<<pgrid, 128, proj_smem>>>(q, k, v, Wq, Wk, Wv, bq, bk, bv);

    dim3 grid(NS / 64 * NSPLIT, NH, NB);     // qt*4 + quarter
    attn_mma_kernel<<<grid, 128, attn_smem>>>(msk);

    merge_kernel<<<2048, 256>>>(out);
}